// round 2
// baseline (speedup 1.0000x reference)
#include <cuda_runtime.h>

// ---------------------------------------------------------------------------
// RAE GRU encoder-decoder, persistent-CTA fp32 kernel with f32x2 packed FMA.
//
//  x[2048,128,38] -> encoder GRU (H=128) -> decoder GRU (autoregressive,
//  feeding back lin projection) -> out[2048,128,38]
//
//  Batch is embarrassingly parallel: 128 CTAs x 16 batch rows, each CTA runs
//  all 256 timesteps locally. Recurrent weights (384x128) live in smem with an
//  XOR swizzle (no padding) so they fit alongside h, lin_W and biases.
//  Input-projection weights (384x38, small K) are streamed from L2 each step
//  from a zero-padded __device__ staging buffer.
// ---------------------------------------------------------------------------

typedef unsigned long long u64;

__device__ __forceinline__ u64 pk2(float lo, float hi) {
    u64 r;
    asm("mov.b64 %0, {%1,%2};" : "=l"(r) : "f"(lo), "f"(hi));
    return r;
}
__device__ __forceinline__ float red2(u64 v) {
    float lo, hi;
    asm("mov.b64 {%0,%1}, %2;" : "=f"(lo), "=f"(hi) : "l"(v));
    return lo + hi;
}
__device__ __forceinline__ void fma2(u64& d, u64 a, u64 b) {
    asm("fma.rn.f32x2 %0, %1, %2, %0;" : "+l"(d) : "l"(a), "l"(b));
}

__device__ __forceinline__ float sigm(float v) {
    return 1.f / (1.f + __expf(-v));
}

constexpr int X    = 38;    // input/output feature dim
constexpr int XP   = 40;    // padded to multiple of 4 floats (16B vectors)
constexpr int H    = 128;   // hidden dim
constexpr int G    = 384;   // 3*H gate rows
constexpr int T    = 128;   // sequence length
constexpr int B    = 2048;  // batch
constexpr int BT   = 16;    // batch rows per CTA
constexpr int NCTA = B / BT;     // 128
constexpr int NTHR = 256;

// padded input-projection weights (zero cols 38,39) staged once per call
__device__ float g_wih_pad[G * XP];
__device__ float g_dwih_pad[G * XP];

__global__ void pad_wih_kernel(const float* __restrict__ ewih,
                               const float* __restrict__ dwih) {
    int i = blockIdx.x * blockDim.x + threadIdx.x;
    if (i < G * XP) {
        int r = i / XP, c = i - r * XP;
        g_wih_pad[i]  = (c < X) ? ewih[r * X + c] : 0.f;
        g_dwih_pad[i] = (c < X) ? dwih[r * X + c] : 0.f;
    }
}

// smem layout (floats):
//  Ws   [384*128] swizzled recurrent weights        49152
//  hS   [16*128]  hidden state                       2048
//  xoS  [16*40]   x_t (enc) / o_prev (dec), padded    640
//  biS  [384]     input-gate bias                     384
//  bhS  [384]     hidden-gate bias                    384
//  lbS  [40]      lin_b padded                         40
//  lwS  [38*128]  lin_W                              4864
constexpr int SM_FLOATS = 49152 + 2048 + 640 + 384 + 384 + 40 + 4864; // 57512
// = 230048 bytes <= 227KB max dynamic smem

__global__ void __launch_bounds__(NTHR, 1)
rae_kernel(const float* __restrict__ x,
           const float* __restrict__ eWhh,
           const float* __restrict__ ebih, const float* __restrict__ ebhh,
           const float* __restrict__ dWhh,
           const float* __restrict__ dbih, const float* __restrict__ dbhh,
           const float* __restrict__ linW, const float* __restrict__ linb,
           float* __restrict__ out) {
    extern __shared__ float sm[];
    float* Ws  = sm;
    float* hS  = Ws + G * H;
    float* xoS = hS + BT * H;
    float* biS = xoS + BT * XP;
    float* bhS = biS + G;
    float* lbS = bhS + G;
    float* lwS = lbS + XP;

    const int tid  = threadIdx.x;
    const int rt   = tid >> 6;        // 0..3  row-tile
    const int ct   = tid & 63;        // 0..63 col-tile
    const int r0   = rt << 2;         // rows r0..r0+3
    const int swz  = (ct & 31) << 2;  // weight swizzle offset for this thread's cols
    const int b0   = blockIdx.x * BT;
    const int lane = tid & 31;

    // ---- stage encoder recurrent weights (swizzled) + biases, zero h ----
    for (int i = tid; i < G * H; i += NTHR) {
        int c = i >> 7, k = i & 127;
        Ws[(c << 7) + (k ^ ((c & 31) << 2))] = eWhh[i];
    }
    for (int i = tid; i < G; i += NTHR) { biS[i] = ebih[i]; bhS[i] = ebhh[i]; }
    for (int i = tid; i < BT * H; i += NTHR) hS[i] = 0.f;
    __syncthreads();

    u64 accI[4][6], accH[4][6];

    // =========================== ENCODER ===========================
    for (int t = 0; t < T; ++t) {
        // stage x_t into padded smem tile
        for (int i = tid; i < BT * XP; i += NTHR) {
            int b = i / XP, k = i - b * XP;
            xoS[i] = (k < X) ? x[((b0 + b) * T + t) * X + k] : 0.f;
        }
        __syncthreads();

        // ---- gi = x_t @ Wih^T + bih  (K = 40 padded, W streamed from L2) ----
        #pragma unroll
        for (int r = 0; r < 4; ++r)
            #pragma unroll
            for (int i = 0; i < 6; ++i) accI[r][i] = pk2(biS[ct + 64 * i], 0.f);
        #pragma unroll
        for (int kb = 0; kb < XP / 4; ++kb) {
            int k = kb << 2;
            ulonglong2 xv[4];
            #pragma unroll
            for (int r = 0; r < 4; ++r)
                xv[r] = *(const ulonglong2*)(xoS + (r0 + r) * XP + k);
            #pragma unroll
            for (int i = 0; i < 6; ++i) {
                ulonglong2 wv = *(const ulonglong2*)(g_wih_pad + (ct + 64 * i) * XP + k);
                #pragma unroll
                for (int r = 0; r < 4; ++r) {
                    fma2(accI[r][i], xv[r].x, wv.x);
                    fma2(accI[r][i], xv[r].y, wv.y);
                }
            }
        }

        // ---- gh = h @ Whh^T + bhh  (K = 128, smem, swizzled, h broadcast) ----
        #pragma unroll
        for (int r = 0; r < 4; ++r)
            #pragma unroll
            for (int i = 0; i < 6; ++i) accH[r][i] = pk2(bhS[ct + 64 * i], 0.f);
        #pragma unroll 4
        for (int kb = 0; kb < H / 4; ++kb) {
            int k = kb << 2;
            ulonglong2 hv[4];
            #pragma unroll
            for (int r = 0; r < 4; ++r)
                hv[r] = *(const ulonglong2*)(hS + (r0 + r) * H + k);
            #pragma unroll
            for (int i = 0; i < 6; ++i) {
                ulonglong2 wv = *(const ulonglong2*)(Ws + ((ct + 64 * i) << 7) + (k ^ swz));
                #pragma unroll
                for (int r = 0; r < 4; ++r) {
                    fma2(accH[r][i], hv[r].x, wv.x);
                    fma2(accH[r][i], hv[r].y, wv.y);
                }
            }
        }
        __syncthreads();

        // ---- GRU elementwise update: this thread owns h cols ct, ct+64 ----
        #pragma unroll
        for (int r = 0; r < 4; ++r) {
            int b = r0 + r;
            #pragma unroll
            for (int jj = 0; jj < 2; ++jj) {
                int j = ct + (jj << 6);
                float rr = sigm(red2(accI[r][jj])     + red2(accH[r][jj]));
                float zz = sigm(red2(accI[r][2 + jj]) + red2(accH[r][2 + jj]));
                float nn = tanhf(red2(accI[r][4 + jj]) + rr * red2(accH[r][4 + jj]));
                float ho = hS[b * H + j];
                hS[b * H + j] = (1.f - zz) * nn + zz * ho;
            }
        }
        __syncthreads();
    }

    // ---- swap to decoder weights ----
    for (int i = tid; i < G * H; i += NTHR) {
        int c = i >> 7, k = i & 127;
        Ws[(c << 7) + (k ^ ((c & 31) << 2))] = dWhh[i];
    }
    for (int i = tid; i < G; i += NTHR) { biS[i] = dbih[i]; bhS[i] = dbhh[i]; }
    for (int i = tid; i < X * H; i += NTHR) lwS[i] = linW[i];
    for (int i = tid; i < XP; i += NTHR) lbS[i] = (i < X) ? linb[i] : 0.f;
    for (int i = tid; i < BT * XP; i += NTHR) xoS[i] = 0.f;  // o_prev(0) = GO = 0
    __syncthreads();

    // projection output assignments for this thread (<=3 of 16*38=608)
    int pb[3], pj[3], np = 0;
    for (int idx = tid; idx < BT * X; idx += NTHR) {
        pb[np] = idx / X;
        pj[np] = idx - pb[np] * X;
        ++np;
    }

    // =========================== DECODER ===========================
    for (int t = 0; t < T; ++t) {
        if (t > 0) {
            // o_prev = h @ lin_W^T + lin_b ; this IS outs[t-1] -> write d_out
            for (int p = 0; p < np; ++p) {
                int b = pb[p], j = pj[p];
                u64 a = pk2(lbS[j], 0.f);
                #pragma unroll 8
                for (int kb = 0; kb < H / 4; ++kb) {
                    int kk = ((kb + lane) & 31) << 2;  // lane rotation: bank-safe
                    ulonglong2 hv = *(const ulonglong2*)(hS + b * H + kk);
                    ulonglong2 wv = *(const ulonglong2*)(lwS + j * H + kk);
                    fma2(a, hv.x, wv.x);
                    fma2(a, hv.y, wv.y);
                }
                float v = red2(a);
                xoS[b * XP + j] = v;
                out[((b0 + b) * T + (t - 1)) * X + j] = v;
            }
        }
        __syncthreads();

        // ---- gi = o_prev @ dec_Wih^T + dec_bih ----
        #pragma unroll
        for (int r = 0; r < 4; ++r)
            #pragma unroll
            for (int i = 0; i < 6; ++i) accI[r][i] = pk2(biS[ct + 64 * i], 0.f);
        #pragma unroll
        for (int kb = 0; kb < XP / 4; ++kb) {
            int k = kb << 2;
            ulonglong2 xv[4];
            #pragma unroll
            for (int r = 0; r < 4; ++r)
                xv[r] = *(const ulonglong2*)(xoS + (r0 + r) * XP + k);
            #pragma unroll
            for (int i = 0; i < 6; ++i) {
                ulonglong2 wv = *(const ulonglong2*)(g_dwih_pad + (ct + 64 * i) * XP + k);
                #pragma unroll
                for (int r = 0; r < 4; ++r) {
                    fma2(accI[r][i], xv[r].x, wv.x);
                    fma2(accI[r][i], xv[r].y, wv.y);
                }
            }
        }

        // ---- gh = h @ dec_Whh^T + dec_bhh ----
        #pragma unroll
        for (int r = 0; r < 4; ++r)
            #pragma unroll
            for (int i = 0; i < 6; ++i) accH[r][i] = pk2(bhS[ct + 64 * i], 0.f);
        #pragma unroll 4
        for (int kb = 0; kb < H / 4; ++kb) {
            int k = kb << 2;
            ulonglong2 hv[4];
            #pragma unroll
            for (int r = 0; r < 4; ++r)
                hv[r] = *(const ulonglong2*)(hS + (r0 + r) * H + k);
            #pragma unroll
            for (int i = 0; i < 6; ++i) {
                ulonglong2 wv = *(const ulonglong2*)(Ws + ((ct + 64 * i) << 7) + (k ^ swz));
                #pragma unroll
                for (int r = 0; r < 4; ++r) {
                    fma2(accH[r][i], hv[r].x, wv.x);
                    fma2(accH[r][i], hv[r].y, wv.y);
                }
            }
        }
        __syncthreads();

        // ---- GRU update ----
        #pragma unroll
        for (int r = 0; r < 4; ++r) {
            int b = r0 + r;
            #pragma unroll
            for (int jj = 0; jj < 2; ++jj) {
                int j = ct + (jj << 6);
                float rr = sigm(red2(accI[r][jj])     + red2(accH[r][jj]));
                float zz = sigm(red2(accI[r][2 + jj]) + red2(accH[r][2 + jj]));
                float nn = tanhf(red2(accI[r][4 + jj]) + rr * red2(accH[r][4 + jj]));
                float ho = hS[b * H + j];
                hS[b * H + j] = (1.f - zz) * nn + zz * ho;
            }
        }
        __syncthreads();
    }

    // ---- final output: outs[T-1] = h_T @ lin_W^T + lin_b ----
    for (int p = 0; p < np; ++p) {
        int b = pb[p], j = pj[p];
        u64 a = pk2(lbS[j], 0.f);
        #pragma unroll 8
        for (int kb = 0; kb < H / 4; ++kb) {
            int kk = ((kb + lane) & 31) << 2;
            ulonglong2 hv = *(const ulonglong2*)(hS + b * H + kk);
            ulonglong2 wv = *(const ulonglong2*)(lwS + j * H + kk);
            fma2(a, hv.x, wv.x);
            fma2(a, hv.y, wv.y);
        }
        out[((b0 + b) * T + (T - 1)) * X + j] = red2(a);
    }
}

extern "C" void kernel_launch(void* const* d_in, const int* in_sizes, int n_in,
                              void* d_out, int out_size) {
    const float* x    = (const float*)d_in[0];
    const float* eWih = (const float*)d_in[1];
    const float* eWhh = (const float*)d_in[2];
    const float* ebih = (const float*)d_in[3];
    const float* ebhh = (const float*)d_in[4];
    const float* dWih = (const float*)d_in[5];
    const float* dWhh = (const float*)d_in[6];
    const float* dbih = (const float*)d_in[7];
    const float* dbhh = (const float*)d_in[8];
    const float* linW = (const float*)d_in[9];
    const float* linb = (const float*)d_in[10];
    float* out = (float*)d_out;

    pad_wih_kernel<<<(G * XP + 255) / 256, 256>>>(eWih, dWih);

    size_t smem = SM_FLOATS * sizeof(float);  // 230048 B
    cudaFuncSetAttribute(rae_kernel, cudaFuncAttributeMaxDynamicSharedMemorySize,
                         (int)smem);
    rae_kernel<<<NCTA, NTHR, smem>>>(x, eWhh, ebih, ebhh,
                                     dWhh, dbih, dbhh, linW, linb, out);
}

// round 4
// speedup vs baseline: 1.2275x; 1.2275x over previous
#include <cuda_runtime.h>

// RAE GRU enc-dec. K0: pad Wih. K1: precompute all encoder gi (parallel GEMM).
// K2: encoder recurrence (512thr, weights in swizzled smem, gi prefetched).
// K3: decoder recurrence with lin_W folded into the recurrent GEMM.

typedef unsigned long long u64;

__device__ __forceinline__ u64 pk2(float lo, float hi) {
    u64 r; asm("mov.b64 %0, {%1,%2};" : "=l"(r) : "f"(lo), "f"(hi)); return r;
}
__device__ __forceinline__ float red2(u64 v) {
    float lo, hi; asm("mov.b64 {%0,%1}, %2;" : "=f"(lo), "=f"(hi) : "l"(v));
    return lo + hi;
}
__device__ __forceinline__ void fma2(u64& d, u64 a, u64 b) {
    asm("fma.rn.f32x2 %0, %1, %2, %0;" : "+l"(d) : "l"(a), "l"(b));
}
__device__ __forceinline__ float sigm(float v) { return 1.f / (1.f + __expf(-v)); }

constexpr int X  = 38;
constexpr int XP = 40;
constexpr int H  = 128;
constexpr int G  = 384;
constexpr int GO = G + X;   // 422: gates + folded lin_W cols
constexpr int T  = 128;
constexpr int B  = 2048;
constexpr int BT = 16;
constexpr int NB = B / BT;  // 128 CTAs

__device__ float g_wih_pad[G * XP];
__device__ float g_dwih_pad[G * XP];
__device__ float g_henc[B * H];
__device__ float g_gi[B * T * G];   // 402MB precomputed encoder gi

// ----------------------------- K0: pad Wih ---------------------------------
__global__ void pad_wih_kernel(const float* __restrict__ ewih,
                               const float* __restrict__ dwih) {
    int i = blockIdx.x * blockDim.x + threadIdx.x;
    if (i < G * XP) {
        int r = i / XP, c = i - r * XP;
        g_wih_pad[i]  = (c < X) ? ewih[r * X + c] : 0.f;
        g_dwih_pad[i] = (c < X) ? dwih[r * X + c] : 0.f;
    }
}

// ------------------- K1: encoder gi precompute GEMM ------------------------
constexpr int K1R = 32;   // (b,t) rows per CTA
__global__ void __launch_bounds__(512, 1)
gi_kernel(const float* __restrict__ x, const float* __restrict__ ebih) {
    __shared__ float xs[K1R * XP];
    const int tid = threadIdx.x;
    const int gr0 = blockIdx.x * K1R;

    for (int i = tid; i < K1R * XP; i += 512) {
        int rr = i / XP, k = i - rr * XP;
        xs[i] = (k < X) ? x[(gr0 + rr) * X + k] : 0.f;
    }
    __syncthreads();

    const int rg = tid >> 7;     // 0..3
    const int ct = tid & 127;
    const int r0 = rg << 3;      // 8 rows

    u64 acc[8][3];
    #pragma unroll
    for (int i = 0; i < 3; ++i) {
        float bi = ebih[ct + (i << 7)];
        #pragma unroll
        for (int r = 0; r < 8; ++r) acc[r][i] = pk2(bi, 0.f);
    }
    #pragma unroll
    for (int kb = 0; kb < XP / 4; ++kb) {
        int k = kb << 2;
        ulonglong2 xv[8];
        #pragma unroll
        for (int r = 0; r < 8; ++r)
            xv[r] = *(const ulonglong2*)(xs + (r0 + r) * XP + k);
        #pragma unroll
        for (int i = 0; i < 3; ++i) {
            ulonglong2 wv = *(const ulonglong2*)(g_wih_pad + (ct + (i << 7)) * XP + k);
            #pragma unroll
            for (int r = 0; r < 8; ++r) {
                fma2(acc[r][i], xv[r].x, wv.x);
                fma2(acc[r][i], xv[r].y, wv.y);
            }
        }
    }
    #pragma unroll
    for (int r = 0; r < 8; ++r) {
        int gr = gr0 + r0 + r;
        int b = gr >> 7, t = gr & (T - 1);      // gr = b*T + t
        int blk = b >> 4, lb = b & 15;
        int base = ((blk * T + t) * BT + lb) * G;
        #pragma unroll
        for (int i = 0; i < 3; ++i) g_gi[base + ct + (i << 7)] = red2(acc[r][i]);
    }
}

// ------------------------- K2: encoder recurrence --------------------------
constexpr int ENC_SMB = (G * H + BT * H) * 4;   // 204800 B

__global__ void __launch_bounds__(512, 1)
enc_kernel(const float* __restrict__ eWhh, const float* __restrict__ ebhh) {
    extern __shared__ float sm[];
    float* Ws = sm;
    float* hS = Ws + G * H;

    const int tid = threadIdx.x;
    const int rg  = tid >> 7;
    const int ct  = tid & 127;
    const int r0  = rg << 2;
    const int swz = (ct & 31) << 2;
    const int blk = blockIdx.x;

    for (int i = tid; i < G * H; i += 512) {
        int c = i >> 7, k = i & 127;
        Ws[(c << 7) + (k ^ ((c & 31) << 2))] = eWhh[i];
    }
    for (int i = tid; i < BT * H; i += 512) hS[i] = 0.f;
    float bh[3];
    #pragma unroll
    for (int i = 0; i < 3; ++i) bh[i] = ebhh[ct + (i << 7)];
    __syncthreads();

    for (int t = 0; t < T; ++t) {
        // dependency-free gi prefetch (overlaps the gh GEMM below)
        float gv[4][3];
        int gbase = (blk * T + t) * BT * G;
        #pragma unroll
        for (int r = 0; r < 4; ++r)
            #pragma unroll
            for (int i = 0; i < 3; ++i)
                gv[r][i] = g_gi[gbase + (r0 + r) * G + ct + (i << 7)];

        u64 aH[4][3];
        #pragma unroll
        for (int r = 0; r < 4; ++r)
            #pragma unroll
            for (int i = 0; i < 3; ++i) aH[r][i] = pk2(bh[i], 0.f);

        #pragma unroll 4
        for (int kb = 0; kb < H / 4; ++kb) {
            int k = kb << 2;
            ulonglong2 hv[4];
            #pragma unroll
            for (int r = 0; r < 4; ++r)
                hv[r] = *(const ulonglong2*)(hS + (r0 + r) * H + k);
            #pragma unroll
            for (int i = 0; i < 3; ++i) {
                ulonglong2 wv = *(const ulonglong2*)(Ws + ((ct + (i << 7)) << 7) + (k ^ swz));
                #pragma unroll
                for (int r = 0; r < 4; ++r) {
                    fma2(aH[r][i], hv[r].x, wv.x);
                    fma2(aH[r][i], hv[r].y, wv.y);
                }
            }
        }
        __syncthreads();

        #pragma unroll
        for (int r = 0; r < 4; ++r) {
            float rr = sigm(gv[r][0] + red2(aH[r][0]));
            float zz = sigm(gv[r][1] + red2(aH[r][1]));
            float nn = tanhf(gv[r][2] + rr * red2(aH[r][2]));
            float ho = hS[(r0 + r) * H + ct];
            hS[(r0 + r) * H + ct] = (1.f - zz) * nn + zz * ho;
        }
        __syncthreads();
    }
    for (int i = tid; i < BT * H; i += 512) g_henc[blk * BT * H + i] = hS[i];
}

// ------------------------- K3: decoder recurrence --------------------------
constexpr int DEC_SMB = (GO * H + BT * H + BT * XP) * 4;  // 226816 B

__global__ void __launch_bounds__(512, 1)
dec_kernel(const float* __restrict__ dWhh,
           const float* __restrict__ dbih, const float* __restrict__ dbhh,
           const float* __restrict__ linW, const float* __restrict__ linb,
           float* __restrict__ out) {
    extern __shared__ float sm[];
    float* Ws = sm;
    float* hS = Ws + GO * H;
    float* oS = hS + BT * H;

    const int tid = threadIdx.x;
    const int rg  = tid >> 7;
    const int ct  = tid & 127;
    const int r0  = rg << 2;
    const int swz = (ct & 31) << 2;
    const int blk = blockIdx.x;
    const bool oc = (ct < X);

    for (int i = tid; i < GO * H; i += 512) {
        int c = i >> 7, k = i & 127;
        float v = (c < G) ? dWhh[i] : linW[(c - G) * H + k];
        Ws[(c << 7) + (k ^ ((c & 31) << 2))] = v;
    }
    for (int i = tid; i < BT * H; i += 512) hS[i] = g_henc[blk * BT * H + i];
    for (int i = tid; i < BT * XP; i += 512) oS[i] = 0.f;   // GO = 0
    float bh[3], bi[3];
    #pragma unroll
    for (int i = 0; i < 3; ++i) { bh[i] = dbhh[ct + (i << 7)]; bi[i] = dbih[ct + (i << 7)]; }
    const float lb = oc ? linb[ct] : 0.f;
    __syncthreads();

    // iteration t: GEMM over h_t yields gh(h_t) AND lin(h_t)=out[t-1] (t>0),
    // which is also the o_prev feeding this step's gi. t==T: emit out[T-1].
    for (int t = 0; t <= T; ++t) {
        u64 aH[4][4];
        #pragma unroll
        for (int r = 0; r < 4; ++r) {
            #pragma unroll
            for (int i = 0; i < 3; ++i) aH[r][i] = pk2(bh[i], 0.f);
            aH[r][3] = pk2(lb, 0.f);
        }
        #pragma unroll 4
        for (int kb = 0; kb < H / 4; ++kb) {
            int k = kb << 2;
            ulonglong2 hv[4];
            #pragma unroll
            for (int r = 0; r < 4; ++r)
                hv[r] = *(const ulonglong2*)(hS + (r0 + r) * H + k);
            #pragma unroll
            for (int i = 0; i < 3; ++i) {
                ulonglong2 wv = *(const ulonglong2*)(Ws + ((ct + (i << 7)) << 7) + (k ^ swz));
                #pragma unroll
                for (int r = 0; r < 4; ++r) {
                    fma2(aH[r][i], hv[r].x, wv.x);
                    fma2(aH[r][i], hv[r].y, wv.y);
                }
            }
            if (oc) {
                ulonglong2 wv = *(const ulonglong2*)(Ws + ((G + ct) << 7) + (k ^ swz));
                #pragma unroll
                for (int r = 0; r < 4; ++r) {
                    fma2(aH[r][3], hv[r].x, wv.x);
                    fma2(aH[r][3], hv[r].y, wv.y);
                }
            }
        }
        float gh0[4], gh1[4], gh2[4];
        #pragma unroll
        for (int r = 0; r < 4; ++r) {
            gh0[r] = red2(aH[r][0]); gh1[r] = red2(aH[r][1]); gh2[r] = red2(aH[r][2]);
        }
        if (oc && t > 0) {
            #pragma unroll
            for (int r = 0; r < 4; ++r) {
                float ov = red2(aH[r][3]);
                oS[(r0 + r) * XP + ct] = ov;
                out[((blk * BT + r0 + r) * T + (t - 1)) * X + ct] = ov;
            }
        }
        if (t == T) break;
        __syncthreads();   // oS published, hS reads done

        // gi = o_prev @ dWih^T + dbih  (K=40; weights stream from hot L2)
        u64 aI[4][3];
        #pragma unroll
        for (int r = 0; r < 4; ++r)
            #pragma unroll
            for (int i = 0; i < 3; ++i) aI[r][i] = pk2(bi[i], 0.f);
        #pragma unroll
        for (int kb = 0; kb < XP / 4; ++kb) {
            int k = kb << 2;
            ulonglong2 xv[4];
            #pragma unroll
            for (int r = 0; r < 4; ++r)
                xv[r] = *(const ulonglong2*)(oS + (r0 + r) * XP + k);
            #pragma unroll
            for (int i = 0; i < 3; ++i) {
                ulonglong2 wv = *(const ulonglong2*)(g_dwih_pad + (ct + (i << 7)) * XP + k);
                #pragma unroll
                for (int r = 0; r < 4; ++r) {
                    fma2(aI[r][i], xv[r].x, wv.x);
                    fma2(aI[r][i], xv[r].y, wv.y);
                }
            }
        }

        #pragma unroll
        for (int r = 0; r < 4; ++r) {
            float rr = sigm(red2(aI[r][0]) + gh0[r]);
            float zz = sigm(red2(aI[r][1]) + gh1[r]);
            float nn = tanhf(red2(aI[r][2]) + rr * gh2[r]);
            float ho = hS[(r0 + r) * H + ct];
            hS[(r0 + r) * H + ct] = (1.f - zz) * nn + zz * ho;
        }
        __syncthreads();
    }
}

extern "C" void kernel_launch(void* const* d_in, const int* in_sizes, int n_in,
                              void* d_out, int out_size) {
    const float* x    = (const float*)d_in[0];
    const float* eWih = (const float*)d_in[1];
    const float* eWhh = (const float*)d_in[2];
    const float* ebih = (const float*)d_in[3];
    const float* ebhh = (const float*)d_in[4];
    const float* dWih = (const float*)d_in[5];
    const float* dWhh = (const float*)d_in[6];
    const float* dbih = (const float*)d_in[7];
    const float* dbhh = (const float*)d_in[8];
    const float* linW = (const float*)d_in[9];
    const float* linb = (const float*)d_in[10];
    float* out = (float*)d_out;

    pad_wih_kernel<<<(G * XP + 255) / 256, 256>>>(eWih, dWih);
    gi_kernel<<<(B * T) / K1R, 512>>>(x, ebih);

    cudaFuncSetAttribute(enc_kernel, cudaFuncAttributeMaxDynamicSharedMemorySize, ENC_SMB);
    enc_kernel<<<NB, 512, ENC_SMB>>>(eWhh, ebhh);

    cudaFuncSetAttribute(dec_kernel, cudaFuncAttributeMaxDynamicSharedMemorySize, DEC_SMB);
    dec_kernel<<<NB, 512, DEC_SMB>>>(dWhh, dbih, dbhh, linW, linb, out);
}

// round 5
// speedup vs baseline: 1.2301x; 1.0021x over previous
#include <cuda_runtime.h>

// RAE GRU enc-dec. K0: pad Wih. K1: precompute all encoder gi (parallel GEMM).
// K2: encoder recurrence (512thr, weights in swizzled smem, gi prefetched).
// K3: decoder recurrence with lin_W folded into the recurrent GEMM.

typedef unsigned long long u64;

__device__ __forceinline__ u64 pk2(float lo, float hi) {
    u64 r; asm("mov.b64 %0, {%1,%2};" : "=l"(r) : "f"(lo), "f"(hi)); return r;
}
__device__ __forceinline__ float red2(u64 v) {
    float lo, hi; asm("mov.b64 {%0,%1}, %2;" : "=f"(lo), "=f"(hi) : "l"(v));
    return lo + hi;
}
__device__ __forceinline__ void fma2(u64& d, u64 a, u64 b) {
    asm("fma.rn.f32x2 %0, %1, %2, %0;" : "+l"(d) : "l"(a), "l"(b));
}
__device__ __forceinline__ float sigm(float v) { return 1.f / (1.f + __expf(-v)); }

constexpr int X  = 38;
constexpr int XP = 40;
constexpr int H  = 128;
constexpr int G  = 384;
constexpr int GO = G + X;   // 422: gates + folded lin_W cols
constexpr int T  = 128;
constexpr int B  = 2048;
constexpr int BT = 16;
constexpr int NB = B / BT;  // 128 CTAs

__device__ float g_wih_pad[G * XP];
__device__ float g_dwih_pad[G * XP];
__device__ float g_henc[B * H];
__device__ float g_gi[B * T * G];   // 402MB precomputed encoder gi

// ----------------------------- K0: pad Wih ---------------------------------
__global__ void pad_wih_kernel(const float* __restrict__ ewih,
                               const float* __restrict__ dwih) {
    int i = blockIdx.x * blockDim.x + threadIdx.x;
    if (i < G * XP) {
        int r = i / XP, c = i - r * XP;
        g_wih_pad[i]  = (c < X) ? ewih[r * X + c] : 0.f;
        g_dwih_pad[i] = (c < X) ? dwih[r * X + c] : 0.f;
    }
}

// ------------------- K1: encoder gi precompute GEMM ------------------------
constexpr int K1R = 32;   // (b,t) rows per CTA
__global__ void __launch_bounds__(512, 1)
gi_kernel(const float* __restrict__ x, const float* __restrict__ ebih) {
    __shared__ float xs[K1R * XP];
    const int tid = threadIdx.x;
    const int gr0 = blockIdx.x * K1R;

    for (int i = tid; i < K1R * XP; i += 512) {
        int rr = i / XP, k = i - rr * XP;
        xs[i] = (k < X) ? x[(gr0 + rr) * X + k] : 0.f;
    }
    __syncthreads();

    const int rg = tid >> 7;     // 0..3
    const int ct = tid & 127;
    const int r0 = rg << 3;      // 8 rows

    u64 acc[8][3];
    #pragma unroll
    for (int i = 0; i < 3; ++i) {
        float bi = ebih[ct + (i << 7)];
        #pragma unroll
        for (int r = 0; r < 8; ++r) acc[r][i] = pk2(bi, 0.f);
    }
    #pragma unroll
    for (int kb = 0; kb < XP / 4; ++kb) {
        int k = kb << 2;
        ulonglong2 xv[8];
        #pragma unroll
        for (int r = 0; r < 8; ++r)
            xv[r] = *(const ulonglong2*)(xs + (r0 + r) * XP + k);
        #pragma unroll
        for (int i = 0; i < 3; ++i) {
            ulonglong2 wv = *(const ulonglong2*)(g_wih_pad + (ct + (i << 7)) * XP + k);
            #pragma unroll
            for (int r = 0; r < 8; ++r) {
                fma2(acc[r][i], xv[r].x, wv.x);
                fma2(acc[r][i], xv[r].y, wv.y);
            }
        }
    }
    #pragma unroll
    for (int r = 0; r < 8; ++r) {
        int gr = gr0 + r0 + r;
        int b = gr >> 7, t = gr & (T - 1);      // gr = b*T + t
        int blk = b >> 4, lb = b & 15;
        int base = ((blk * T + t) * BT + lb) * G;
        #pragma unroll
        for (int i = 0; i < 3; ++i) g_gi[base + ct + (i << 7)] = red2(acc[r][i]);
    }
}

// ------------------------- K2: encoder recurrence --------------------------
constexpr int ENC_SMB = (G * H + BT * H) * 4;   // 204800 B

__global__ void __launch_bounds__(512, 1)
enc_kernel(const float* __restrict__ eWhh, const float* __restrict__ ebhh) {
    extern __shared__ float sm[];
    float* Ws = sm;
    float* hS = Ws + G * H;

    const int tid = threadIdx.x;
    const int rg  = tid >> 7;
    const int ct  = tid & 127;
    const int r0  = rg << 2;
    const int swz = (ct & 31) << 2;
    const int blk = blockIdx.x;

    for (int i = tid; i < G * H; i += 512) {
        int c = i >> 7, k = i & 127;
        Ws[(c << 7) + (k ^ ((c & 31) << 2))] = eWhh[i];
    }
    for (int i = tid; i < BT * H; i += 512) hS[i] = 0.f;
    float bh[3];
    #pragma unroll
    for (int i = 0; i < 3; ++i) bh[i] = ebhh[ct + (i << 7)];
    __syncthreads();

    for (int t = 0; t < T; ++t) {
        // dependency-free gi prefetch (overlaps the gh GEMM below)
        float gv[4][3];
        int gbase = (blk * T + t) * BT * G;
        #pragma unroll
        for (int r = 0; r < 4; ++r)
            #pragma unroll
            for (int i = 0; i < 3; ++i)
                gv[r][i] = g_gi[gbase + (r0 + r) * G + ct + (i << 7)];

        u64 aH[4][3];
        #pragma unroll
        for (int r = 0; r < 4; ++r)
            #pragma unroll
            for (int i = 0; i < 3; ++i) aH[r][i] = pk2(bh[i], 0.f);

        #pragma unroll 4
        for (int kb = 0; kb < H / 4; ++kb) {
            int k = kb << 2;
            ulonglong2 hv[4];
            #pragma unroll
            for (int r = 0; r < 4; ++r)
                hv[r] = *(const ulonglong2*)(hS + (r0 + r) * H + k);
            #pragma unroll
            for (int i = 0; i < 3; ++i) {
                ulonglong2 wv = *(const ulonglong2*)(Ws + ((ct + (i << 7)) << 7) + (k ^ swz));
                #pragma unroll
                for (int r = 0; r < 4; ++r) {
                    fma2(aH[r][i], hv[r].x, wv.x);
                    fma2(aH[r][i], hv[r].y, wv.y);
                }
            }
        }
        __syncthreads();

        #pragma unroll
        for (int r = 0; r < 4; ++r) {
            float rr = sigm(gv[r][0] + red2(aH[r][0]));
            float zz = sigm(gv[r][1] + red2(aH[r][1]));
            float nn = tanhf(gv[r][2] + rr * red2(aH[r][2]));
            float ho = hS[(r0 + r) * H + ct];
            hS[(r0 + r) * H + ct] = (1.f - zz) * nn + zz * ho;
        }
        __syncthreads();
    }
    for (int i = tid; i < BT * H; i += 512) g_henc[blk * BT * H + i] = hS[i];
}

// ------------------------- K3: decoder recurrence --------------------------
constexpr int DEC_SMB = (GO * H + BT * H + BT * XP) * 4;  // 226816 B

__global__ void __launch_bounds__(512, 1)
dec_kernel(const float* __restrict__ dWhh,
           const float* __restrict__ dbih, const float* __restrict__ dbhh,
           const float* __restrict__ linW, const float* __restrict__ linb,
           float* __restrict__ out) {
    extern __shared__ float sm[];
    float* Ws = sm;
    float* hS = Ws + GO * H;
    float* oS = hS + BT * H;

    const int tid = threadIdx.x;
    const int rg  = tid >> 7;
    const int ct  = tid & 127;
    const int r0  = rg << 2;
    const int swz = (ct & 31) << 2;
    const int blk = blockIdx.x;
    const bool oc = (ct < X);

    for (int i = tid; i < GO * H; i += 512) {
        int c = i >> 7, k = i & 127;
        float v = (c < G) ? dWhh[i] : linW[(c - G) * H + k];
        Ws[(c << 7) + (k ^ ((c & 31) << 2))] = v;
    }
    for (int i = tid; i < BT * H; i += 512) hS[i] = g_henc[blk * BT * H + i];
    for (int i = tid; i < BT * XP; i += 512) oS[i] = 0.f;   // GO = 0
    float bh[3], bi[3];
    #pragma unroll
    for (int i = 0; i < 3; ++i) { bh[i] = dbhh[ct + (i << 7)]; bi[i] = dbih[ct + (i << 7)]; }
    const float lb = oc ? linb[ct] : 0.f;
    __syncthreads();

    // iteration t: GEMM over h_t yields gh(h_t) AND lin(h_t)=out[t-1] (t>0),
    // which is also the o_prev feeding this step's gi. t==T: emit out[T-1].
    for (int t = 0; t <= T; ++t) {
        u64 aH[4][4];
        #pragma unroll
        for (int r = 0; r < 4; ++r) {
            #pragma unroll
            for (int i = 0; i < 3; ++i) aH[r][i] = pk2(bh[i], 0.f);
            aH[r][3] = pk2(lb, 0.f);
        }
        #pragma unroll 4
        for (int kb = 0; kb < H / 4; ++kb) {
            int k = kb << 2;
            ulonglong2 hv[4];
            #pragma unroll
            for (int r = 0; r < 4; ++r)
                hv[r] = *(const ulonglong2*)(hS + (r0 + r) * H + k);
            #pragma unroll
            for (int i = 0; i < 3; ++i) {
                ulonglong2 wv = *(const ulonglong2*)(Ws + ((ct + (i << 7)) << 7) + (k ^ swz));
                #pragma unroll
                for (int r = 0; r < 4; ++r) {
                    fma2(aH[r][i], hv[r].x, wv.x);
                    fma2(aH[r][i], hv[r].y, wv.y);
                }
            }
            if (oc) {
                ulonglong2 wv = *(const ulonglong2*)(Ws + ((G + ct) << 7) + (k ^ swz));
                #pragma unroll
                for (int r = 0; r < 4; ++r) {
                    fma2(aH[r][3], hv[r].x, wv.x);
                    fma2(aH[r][3], hv[r].y, wv.y);
                }
            }
        }
        float gh0[4], gh1[4], gh2[4];
        #pragma unroll
        for (int r = 0; r < 4; ++r) {
            gh0[r] = red2(aH[r][0]); gh1[r] = red2(aH[r][1]); gh2[r] = red2(aH[r][2]);
        }
        if (oc && t > 0) {
            #pragma unroll
            for (int r = 0; r < 4; ++r) {
                float ov = red2(aH[r][3]);
                oS[(r0 + r) * XP + ct] = ov;
                out[((blk * BT + r0 + r) * T + (t - 1)) * X + ct] = ov;
            }
        }
        if (t == T) break;
        __syncthreads();   // oS published, hS reads done

        // gi = o_prev @ dWih^T + dbih  (K=40; weights stream from hot L2)
        u64 aI[4][3];
        #pragma unroll
        for (int r = 0; r < 4; ++r)
            #pragma unroll
            for (int i = 0; i < 3; ++i) aI[r][i] = pk2(bi[i], 0.f);
        #pragma unroll
        for (int kb = 0; kb < XP / 4; ++kb) {
            int k = kb << 2;
            ulonglong2 xv[4];
            #pragma unroll
            for (int r = 0; r < 4; ++r)
                xv[r] = *(const ulonglong2*)(oS + (r0 + r) * XP + k);
            #pragma unroll
            for (int i = 0; i < 3; ++i) {
                ulonglong2 wv = *(const ulonglong2*)(g_dwih_pad + (ct + (i << 7)) * XP + k);
                #pragma unroll
                for (int r = 0; r < 4; ++r) {
                    fma2(aI[r][i], xv[r].x, wv.x);
                    fma2(aI[r][i], xv[r].y, wv.y);
                }
            }
        }

        #pragma unroll
        for (int r = 0; r < 4; ++r) {
            float rr = sigm(red2(aI[r][0]) + gh0[r]);
            float zz = sigm(red2(aI[r][1]) + gh1[r]);
            float nn = tanhf(red2(aI[r][2]) + rr * gh2[r]);
            float ho = hS[(r0 + r) * H + ct];
            hS[(r0 + r) * H + ct] = (1.f - zz) * nn + zz * ho;
        }
        __syncthreads();
    }
}

extern "C" void kernel_launch(void* const* d_in, const int* in_sizes, int n_in,
                              void* d_out, int out_size) {
    const float* x    = (const float*)d_in[0];
    const float* eWih = (const float*)d_in[1];
    const float* eWhh = (const float*)d_in[2];
    const float* ebih = (const float*)d_in[3];
    const float* ebhh = (const float*)d_in[4];
    const float* dWih = (const float*)d_in[5];
    const float* dWhh = (const float*)d_in[6];
    const float* dbih = (const float*)d_in[7];
    const float* dbhh = (const float*)d_in[8];
    const float* linW = (const float*)d_in[9];
    const float* linb = (const float*)d_in[10];
    float* out = (float*)d_out;

    pad_wih_kernel<<<(G * XP + 255) / 256, 256>>>(eWih, dWih);
    gi_kernel<<<(B * T) / K1R, 512>>>(x, ebih);

    cudaFuncSetAttribute(enc_kernel, cudaFuncAttributeMaxDynamicSharedMemorySize, ENC_SMB);
    enc_kernel<<<NB, 512, ENC_SMB>>>(eWhh, ebhh);

    cudaFuncSetAttribute(dec_kernel, cudaFuncAttributeMaxDynamicSharedMemorySize, DEC_SMB);
    dec_kernel<<<NB, 512, DEC_SMB>>>(dWhh, dbih, dbhh, linW, linb, out);
}

// round 6
// speedup vs baseline: 1.8314x; 1.4889x over previous
#include <cuda_runtime.h>

// RAE GRU enc-dec. K0: pad+transpose Wih. K1: precompute all encoder gi.
// K2: encoder recurrence (ping-pong h, 1 barrier/step).
// K3: decoder recurrence (lin_W folded into GEMM, coalesced gi weights).

typedef unsigned long long u64;

__device__ __forceinline__ u64 pk2(float lo, float hi) {
    u64 r; asm("mov.b64 %0, {%1,%2};" : "=l"(r) : "f"(lo), "f"(hi)); return r;
}
__device__ __forceinline__ float red2(u64 v) {
    float lo, hi; asm("mov.b64 {%0,%1}, %2;" : "=f"(lo), "=f"(hi) : "l"(v));
    return lo + hi;
}
__device__ __forceinline__ void fma2(u64& d, u64 a, u64 b) {
    asm("fma.rn.f32x2 %0, %1, %2, %0;" : "+l"(d) : "l"(a), "l"(b));
}
__device__ __forceinline__ float sigm(float v) { return 1.f / (1.f + __expf(-v)); }

constexpr int X  = 38;
constexpr int XP = 40;
constexpr int H  = 128;
constexpr int G  = 384;
constexpr int GO = G + X;   // 422: gates + folded lin_W cols
constexpr int T  = 128;
constexpr int B  = 2048;
constexpr int BT = 16;
constexpr int NB = B / BT;  // 128 CTAs

// transposed padded Wih staging: [kb][col][kk], kb=k/4, kk=k%4  (coalesced 16B/col)
__device__ float g_wih_t[(XP / 4) * G * 4];
__device__ float g_dwih_t[(XP / 4) * G * 4];
__device__ float g_henc[B * H];
__device__ float g_gi[B * T * G];

// ----------------------------- K0: pad/transpose Wih -----------------------
__global__ void pad_wih_kernel(const float* __restrict__ ewih,
                               const float* __restrict__ dwih) {
    int i = blockIdx.x * blockDim.x + threadIdx.x;
    if (i < G * XP) {
        int col = i / XP, k = i - col * XP;
        int dst = (k >> 2) * (G * 4) + col * 4 + (k & 3);
        g_wih_t[dst]  = (k < X) ? ewih[col * X + k] : 0.f;
        g_dwih_t[dst] = (k < X) ? dwih[col * X + k] : 0.f;
    }
}

// ------------------- K1: encoder gi precompute GEMM ------------------------
constexpr int K1R = 32;
__global__ void __launch_bounds__(512, 1)
gi_kernel(const float* __restrict__ x, const float* __restrict__ ebih) {
    __shared__ float xs[K1R * XP];
    const int tid = threadIdx.x;
    const int gr0 = blockIdx.x * K1R;

    for (int i = tid; i < K1R * XP; i += 512) {
        int rr = i / XP, k = i - rr * XP;
        xs[i] = (k < X) ? x[(gr0 + rr) * X + k] : 0.f;
    }
    __syncthreads();

    const int rg = tid >> 7;
    const int ct = tid & 127;
    const int r0 = rg << 3;

    u64 acc[8][3];
    #pragma unroll
    for (int i = 0; i < 3; ++i) {
        float bi = ebih[ct + (i << 7)];
        #pragma unroll
        for (int r = 0; r < 8; ++r) acc[r][i] = pk2(bi, 0.f);
    }
    #pragma unroll
    for (int kb = 0; kb < XP / 4; ++kb) {
        int k = kb << 2;
        ulonglong2 xv[8];
        #pragma unroll
        for (int r = 0; r < 8; ++r)
            xv[r] = *(const ulonglong2*)(xs + (r0 + r) * XP + k);
        #pragma unroll
        for (int i = 0; i < 3; ++i) {
            ulonglong2 wv = *(const ulonglong2*)(g_wih_t + kb * (G * 4) + (ct + (i << 7)) * 4);
            #pragma unroll
            for (int r = 0; r < 8; ++r) {
                fma2(acc[r][i], xv[r].x, wv.x);
                fma2(acc[r][i], xv[r].y, wv.y);
            }
        }
    }
    #pragma unroll
    for (int r = 0; r < 8; ++r) {
        int gr = gr0 + r0 + r;
        int b = gr >> 7, t = gr & (T - 1);
        int blk = b >> 4, lb = b & 15;
        int base = ((blk * T + t) * BT + lb) * G;
        #pragma unroll
        for (int i = 0; i < 3; ++i) g_gi[base + ct + (i << 7)] = red2(acc[r][i]);
    }
}

// ------------------------- K2: encoder recurrence --------------------------
constexpr int ENC_SMB = (G * H + 2 * BT * H) * 4;   // 212992 B

__global__ void __launch_bounds__(512, 1)
enc_kernel(const float* __restrict__ eWhh, const float* __restrict__ ebhh) {
    extern __shared__ float sm[];
    float* Ws = sm;
    float* hA = Ws + G * H;
    float* hB = hA + BT * H;

    const int tid = threadIdx.x;
    const int rg  = tid >> 7;
    const int ct  = tid & 127;
    const int r0  = rg << 2;
    const int swz = (ct & 31) << 2;
    const int blk = blockIdx.x;

    for (int i = tid; i < G * H; i += 512) {
        int c = i >> 7, k = i & 127;
        Ws[(c << 7) + (k ^ ((c & 31) << 2))] = eWhh[i];
    }
    for (int i = tid; i < BT * H; i += 512) hA[i] = 0.f;
    float bh[3];
    #pragma unroll
    for (int i = 0; i < 3; ++i) bh[i] = ebhh[ct + (i << 7)];
    __syncthreads();

    float* hR = hA;
    float* hW = hB;

    for (int t = 0; t < T; ++t) {
        // dependency-free gi prefetch (overlaps the gh GEMM)
        float gv[4][3];
        int gbase = (blk * T + t) * BT * G;
        #pragma unroll
        for (int r = 0; r < 4; ++r)
            #pragma unroll
            for (int i = 0; i < 3; ++i)
                gv[r][i] = g_gi[gbase + (r0 + r) * G + ct + (i << 7)];

        u64 aH[4][3];
        #pragma unroll
        for (int r = 0; r < 4; ++r)
            #pragma unroll
            for (int i = 0; i < 3; ++i) aH[r][i] = pk2(bh[i], 0.f);

        #pragma unroll 8
        for (int kb = 0; kb < H / 4; ++kb) {
            int k = kb << 2;
            ulonglong2 hv[4];
            #pragma unroll
            for (int r = 0; r < 4; ++r)
                hv[r] = *(const ulonglong2*)(hR + (r0 + r) * H + k);
            #pragma unroll
            for (int i = 0; i < 3; ++i) {
                ulonglong2 wv = *(const ulonglong2*)(Ws + ((ct + (i << 7)) << 7) + (k ^ swz));
                #pragma unroll
                for (int r = 0; r < 4; ++r) {
                    fma2(aH[r][i], hv[r].x, wv.x);
                    fma2(aH[r][i], hv[r].y, wv.y);
                }
            }
        }

        // update into the inactive buffer: no read-write hazard, 1 barrier/step
        #pragma unroll
        for (int r = 0; r < 4; ++r) {
            float rr = sigm(gv[r][0] + red2(aH[r][0]));
            float zz = sigm(gv[r][1] + red2(aH[r][1]));
            float nn = tanhf(gv[r][2] + rr * red2(aH[r][2]));
            float ho = hR[(r0 + r) * H + ct];
            hW[(r0 + r) * H + ct] = (1.f - zz) * nn + zz * ho;
        }
        __syncthreads();
        float* tmp = hR; hR = hW; hW = tmp;
    }
    for (int i = tid; i < BT * H; i += 512) g_henc[blk * BT * H + i] = hR[i];
}

// ------------------------- K3: decoder recurrence --------------------------
constexpr int DEC_SMB = (GO * H + BT * H + BT * XP) * 4;  // 226816 B

__global__ void __launch_bounds__(512, 1)
dec_kernel(const float* __restrict__ dWhh,
           const float* __restrict__ dbih, const float* __restrict__ dbhh,
           const float* __restrict__ linW, const float* __restrict__ linb,
           float* __restrict__ out) {
    extern __shared__ float sm[];
    float* Ws = sm;
    float* hS = Ws + GO * H;
    float* oS = hS + BT * H;

    const int tid = threadIdx.x;
    const int rg  = tid >> 7;
    const int ct  = tid & 127;
    const int r0  = rg << 2;
    const int swz = (ct & 31) << 2;
    const int blk = blockIdx.x;
    const bool oc = (ct < X);

    for (int i = tid; i < GO * H; i += 512) {
        int c = i >> 7, k = i & 127;
        float v = (c < G) ? dWhh[i] : linW[(c - G) * H + k];
        Ws[(c << 7) + (k ^ ((c & 31) << 2))] = v;
    }
    for (int i = tid; i < BT * H; i += 512) hS[i] = g_henc[blk * BT * H + i];
    for (int i = tid; i < BT * XP; i += 512) oS[i] = 0.f;   // GO = 0
    float bh[3], bi[3];
    #pragma unroll
    for (int i = 0; i < 3; ++i) { bh[i] = dbhh[ct + (i << 7)]; bi[i] = dbih[ct + (i << 7)]; }
    const float lb = oc ? linb[ct] : 0.f;
    __syncthreads();

    // iter t: GEMM over h_{t-1} -> gh gates + o_{t-1}=lin(h_{t-1})=out[t-1];
    // gi from o_{t-1}; update h. iter t==T only emits out[T-1].
    for (int t = 0; t <= T; ++t) {
        u64 aH[4][3];
        u64 aL[4];
        #pragma unroll
        for (int r = 0; r < 4; ++r) {
            #pragma unroll
            for (int i = 0; i < 3; ++i) aH[r][i] = pk2(bh[i], 0.f);
            aL[r] = pk2(lb, 0.f);
        }
        #pragma unroll 8
        for (int kb = 0; kb < H / 4; ++kb) {
            int k = kb << 2;
            ulonglong2 hv[4];
            #pragma unroll
            for (int r = 0; r < 4; ++r)
                hv[r] = *(const ulonglong2*)(hS + (r0 + r) * H + k);
            #pragma unroll
            for (int i = 0; i < 3; ++i) {
                ulonglong2 wv = *(const ulonglong2*)(Ws + ((ct + (i << 7)) << 7) + (k ^ swz));
                #pragma unroll
                for (int r = 0; r < 4; ++r) {
                    fma2(aH[r][i], hv[r].x, wv.x);
                    fma2(aH[r][i], hv[r].y, wv.y);
                }
            }
            if (oc) {
                ulonglong2 wl = *(const ulonglong2*)(Ws + ((G + ct) << 7) + (k ^ swz));
                #pragma unroll
                for (int r = 0; r < 4; ++r) {
                    fma2(aL[r], hv[r].x, wl.x);
                    fma2(aL[r], hv[r].y, wl.y);
                }
            }
        }
        float gh0[4], gh1[4], gh2[4];
        #pragma unroll
        for (int r = 0; r < 4; ++r) {
            gh0[r] = red2(aH[r][0]); gh1[r] = red2(aH[r][1]); gh2[r] = red2(aH[r][2]);
        }
        if (oc && t > 0) {
            #pragma unroll
            for (int r = 0; r < 4; ++r) {
                float ov = red2(aL[r]);
                oS[(r0 + r) * XP + ct] = ov;
                out[((blk * BT + r0 + r) * T + (t - 1)) * X + ct] = ov;
            }
        }
        if (t == T) break;
        __syncthreads();   // oS published, hS reads complete

        // gi = o_prev @ dWih^T + dbih  (coalesced transposed weights from L2)
        u64 aI[4][3];
        #pragma unroll
        for (int r = 0; r < 4; ++r)
            #pragma unroll
            for (int i = 0; i < 3; ++i) aI[r][i] = pk2(bi[i], 0.f);
        #pragma unroll
        for (int kb = 0; kb < XP / 4; ++kb) {
            int k = kb << 2;
            ulonglong2 xv[4];
            #pragma unroll
            for (int r = 0; r < 4; ++r)
                xv[r] = *(const ulonglong2*)(oS + (r0 + r) * XP + k);
            #pragma unroll
            for (int i = 0; i < 3; ++i) {
                ulonglong2 wv = *(const ulonglong2*)(g_dwih_t + kb * (G * 4) + (ct + (i << 7)) * 4);
                #pragma unroll
                for (int r = 0; r < 4; ++r) {
                    fma2(aI[r][i], xv[r].x, wv.x);
                    fma2(aI[r][i], xv[r].y, wv.y);
                }
            }
        }

        #pragma unroll
        for (int r = 0; r < 4; ++r) {
            float rr = sigm(red2(aI[r][0]) + gh0[r]);
            float zz = sigm(red2(aI[r][1]) + gh1[r]);
            float nn = tanhf(red2(aI[r][2]) + rr * gh2[r]);
            float ho = hS[(r0 + r) * H + ct];
            hS[(r0 + r) * H + ct] = (1.f - zz) * nn + zz * ho;
        }
        __syncthreads();
    }
}

extern "C" void kernel_launch(void* const* d_in, const int* in_sizes, int n_in,
                              void* d_out, int out_size) {
    const float* x    = (const float*)d_in[0];
    const float* eWih = (const float*)d_in[1];
    const float* eWhh = (const float*)d_in[2];
    const float* ebih = (const float*)d_in[3];
    const float* ebhh = (const float*)d_in[4];
    const float* dWih = (const float*)d_in[5];
    const float* dWhh = (const float*)d_in[6];
    const float* dbih = (const float*)d_in[7];
    const float* dbhh = (const float*)d_in[8];
    const float* linW = (const float*)d_in[9];
    const float* linb = (const float*)d_in[10];
    float* out = (float*)d_out;

    pad_wih_kernel<<<(G * XP + 255) / 256, 256>>>(eWih, dWih);
    gi_kernel<<<(B * T) / K1R, 512>>>(x, ebih);

    cudaFuncSetAttribute(enc_kernel, cudaFuncAttributeMaxDynamicSharedMemorySize, ENC_SMB);
    enc_kernel<<<NB, 512, ENC_SMB>>>(eWhh, ebhh);

    cudaFuncSetAttribute(dec_kernel, cudaFuncAttributeMaxDynamicSharedMemorySize, DEC_SMB);
    dec_kernel<<<NB, 512, DEC_SMB>>>(dWhh, dbih, dbhh, linW, linb, out);
}